// round 7
// baseline (speedup 1.0000x reference)
#include <cuda_runtime.h>
#include <cuda_bf16.h>
#include <stdint.h>

// ---------------------------------------------------------------------------
// HeteroGraphSAGE, 2 layers, 4 node types, 8 relations.
// agg[d] = Wr * (inv[d] * sum_e w_e * x[src]) -> CSR gather (no atomics),
// everything in split-bf16 (hi+lo, fp32-accurate to ~2^-16); one K-concat
// mma.sync GEMM per dst type with cp.async double-buffered fills.
// (tcgen05 unavailable: harness PTX targets compute_103, not sm_103a.)
// ---------------------------------------------------------------------------

#define NU 200000
#define NP 100000
#define NC 2000
#define NQ 50000
#define NTOT 352000
#define HID 128

#define NROWS 802000
#define ETOT  2400000
#define NWCHUNK 24

#define LDS 72              // bf16 per smem row (64 data + 8 pad -> 144B pitch)
#define LDSB 144
#define TILE_B (128 * LDSB)          // 18432 B per 128x64 bf16 tile
#define STAGE_B (4 * TILE_B)         // Ah, Al, Wh, Wl
#define GSMEM (2 * STAGE_B)          // двойной buffer: 147456 B

// device globals (allocation-free scratch)
__device__ __nv_bfloat16 g_ahi[(size_t)NROWS * HID];
__device__ __nv_bfloat16 g_alo[(size_t)NROWS * HID];
__device__ __nv_bfloat16 g_xhi[(size_t)NTOT * HID];   // x0 split, then h split (in-place)
__device__ __nv_bfloat16 g_xlo[(size_t)NTOT * HID];
__device__ int   g_cnt[NROWS];
__device__ int   g_rowptr[NROWS + 1];
__device__ int   g_cursor[NROWS];
__device__ int   g_srcg[ETOT];
__device__ float g_wg[ETOT];
__device__ int   g_bsums[512];
__device__ float g_wsum[2 * 4 * HID * HID];
__device__ float g_bsum[2 * 4 * HID];
__device__ __nv_bfloat16 g_wh[NWCHUNK * HID * HID];
__device__ __nv_bfloat16 g_wl[NWCHUNK * HID * HID];

// ---------------------------------------------------------------------------
// PTX helpers
// ---------------------------------------------------------------------------
#define LDSM4(R, addr)                                                          \
    asm volatile("ldmatrix.sync.aligned.m8n8.x4.shared.b16 {%0,%1,%2,%3}, [%4];" \
                 : "=r"((R)[0]), "=r"((R)[1]), "=r"((R)[2]), "=r"((R)[3])        \
                 : "r"(addr))

#define MMA16816(C, A, B0, B1)                                                  \
    asm volatile("mma.sync.aligned.m16n8k16.row.col.f32.bf16.bf16.f32 "         \
                 "{%0,%1,%2,%3},{%4,%5,%6,%7},{%8,%9},{%0,%1,%2,%3};"           \
                 : "+f"((C)[0]), "+f"((C)[1]), "+f"((C)[2]), "+f"((C)[3])        \
                 : "r"((A)[0]), "r"((A)[1]), "r"((A)[2]), "r"((A)[3]),           \
                   "r"(B0), "r"(B1))

__device__ __forceinline__ void cpa16(uint32_t dst, const void* src, uint32_t sz)
{
    asm volatile("cp.async.cg.shared.global [%0], [%1], 16, %2;"
                 :: "r"(dst), "l"(src), "r"(sz) : "memory");
}

__device__ __forceinline__ uint32_t pack_bf16(__nv_bfloat16 a, __nv_bfloat16 b)
{
    __nv_bfloat162 p = __halves2bfloat162(a, b);
    return *reinterpret_cast<uint32_t*>(&p);
}

__device__ __forceinline__ void split_pair(float x, float y, uint32_t& hi, uint32_t& lo)
{
    __nv_bfloat16 hx = __float2bfloat16(x);
    __nv_bfloat16 hy = __float2bfloat16(y);
    __nv_bfloat16 lx = __float2bfloat16(x - __bfloat162float(hx));
    __nv_bfloat16 ly = __float2bfloat16(y - __bfloat162float(hy));
    hi = pack_bf16(hx, hy);
    lo = pack_bf16(lx, ly);
}

// ---------------------------------------------------------------------------
// Multi-chunk tensor-core GEMM (bf16x3 split), cp.async double-buffered:
//   C = bias + sum_ch A_ch @ W_ch^T   (each chunk K=128 as 2 stages of K=64)
// Block tile 128x128, 8 warps (4m x 2n). All inputs pre-split bf16.
// ---------------------------------------------------------------------------
struct GemmArgs {
    const __nv_bfloat16 *A0h, *A0l, *A1h, *A1l, *A2h, *A2l, *A3h, *A3l;
    const __nv_bfloat16 *W0h, *W0l, *W1h, *W1l, *W2h, *W2l, *W3h, *W3l;
};

__device__ __forceinline__ void issue_stage(const GemmArgs& p, int s, uint32_t bufb,
                                            int bm, int n, int tid)
{
    int ch = s >> 1;
    const __nv_bfloat16* Ah = (ch == 0) ? p.A0h : (ch == 1) ? p.A1h
                            : (ch == 2) ? p.A2h : p.A3h;
    const __nv_bfloat16* Al = (ch == 0) ? p.A0l : (ch == 1) ? p.A1l
                            : (ch == 2) ? p.A2l : p.A3l;
    const __nv_bfloat16* Wh = (ch == 0) ? p.W0h : (ch == 1) ? p.W1h
                            : (ch == 2) ? p.W2h : p.W3h;
    const __nv_bfloat16* Wl = (ch == 0) ? p.W0l : (ch == 1) ? p.W1l
                            : (ch == 2) ? p.W2l : p.W3l;
    int kE = (s & 1) * 64;

#pragma unroll
    for (int it = 0; it < 4; it++) {
        int idx = tid + it * 256;          // granule 0..1023
        int r   = idx >> 3;                // row 0..127
        int c16 = idx & 7;                 // 16B column group
        uint32_t so = r * LDSB + c16 * 16;
        int grow = bm + r;
        int rowc = (grow < n) ? grow : (n - 1);
        uint32_t ok = (grow < n) ? 16u : 0u;
        size_t ga = (size_t)rowc * HID + kE + c16 * 8;
        size_t gw = (size_t)r * HID + kE + c16 * 8;
        cpa16(bufb + so,              Ah + ga, ok);
        cpa16(bufb + TILE_B + so,     Al + ga, ok);
        cpa16(bufb + 2 * TILE_B + so, Wh + gw, 16u);
        cpa16(bufb + 3 * TILE_B + so, Wl + gw, 16u);
    }
    asm volatile("cp.async.commit_group;" ::: "memory");
}

__global__ void __launch_bounds__(256, 1)
gemm_mma(GemmArgs p, int nch, const float* __restrict__ bias,
         float* __restrict__ C32, __nv_bfloat16* __restrict__ Chi,
         __nv_bfloat16* __restrict__ Clo, int n, int dorelu)
{
    extern __shared__ __nv_bfloat16 smem[];
    uint32_t sb = (uint32_t)__cvta_generic_to_shared(smem);

    const int tid  = threadIdx.x;
    const int lane = tid & 31;
    const int warp = tid >> 5;
    const int wm = warp >> 1;
    const int wn = warp & 1;
    const int bm = blockIdx.x * 128;

    float c[2][8][4];
#pragma unroll
    for (int i = 0; i < 2; i++)
#pragma unroll
        for (int j = 0; j < 8; j++)
#pragma unroll
            for (int q = 0; q < 4; q++) c[i][j][q] = 0.f;

    const int nst = nch * 2;

    issue_stage(p, 0, sb, bm, n, tid);
    issue_stage(p, 1, sb + STAGE_B, bm, n, tid);

    for (int s = 0; s < nst; s++) {
        if (s + 1 < nst)
            asm volatile("cp.async.wait_group 1;" ::: "memory");
        else
            asm volatile("cp.async.wait_group 0;" ::: "memory");
        __syncthreads();

        uint32_t bufb = sb + (s & 1) * STAGE_B;
        uint32_t sA = bufb;
        uint32_t sW = bufb + 2 * TILE_B;

#pragma unroll
        for (int ks = 0; ks < 4; ks++) {
            uint32_t ah[2][4], al[2][4], bh[4][4], bl[4][4];
#pragma unroll
            for (int i = 0; i < 2; i++) {
                int r   = wm * 32 + i * 16 + (lane & 15);
                int kby = ks * 32 + ((lane >> 4) << 4);
                uint32_t ad = sA + r * LDSB + kby;
                LDSM4(ah[i], ad);
                LDSM4(al[i], ad + TILE_B);
            }
#pragma unroll
            for (int pq = 0; pq < 4; pq++) {
                int nr  = wn * 64 + (2 * pq + (lane >> 4)) * 8 + (lane & 7);
                int kby = ks * 32 + ((lane >> 3) & 1) * 16;
                uint32_t ad = sW + nr * LDSB + kby;
                LDSM4(bh[pq], ad);
                LDSM4(bl[pq], ad + TILE_B);
            }
#pragma unroll
            for (int i = 0; i < 2; i++)
#pragma unroll
                for (int j = 0; j < 8; j++) {
                    const uint32_t* b = bh[j >> 1] + (j & 1) * 2;
                    MMA16816(c[i][j], ah[i], b[0], b[1]);
                }
#pragma unroll
            for (int i = 0; i < 2; i++)
#pragma unroll
                for (int j = 0; j < 8; j++) {
                    const uint32_t* b = bl[j >> 1] + (j & 1) * 2;
                    MMA16816(c[i][j], ah[i], b[0], b[1]);
                }
#pragma unroll
            for (int i = 0; i < 2; i++)
#pragma unroll
                for (int j = 0; j < 8; j++) {
                    const uint32_t* b = bh[j >> 1] + (j & 1) * 2;
                    MMA16816(c[i][j], al[i], b[0], b[1]);
                }
        }
        __syncthreads();
        if (s + 2 < nst)
            issue_stage(p, s + 2, sb + (s & 1) * STAGE_B, bm, n, tid);
    }

    // ---- epilogue ----
    const int g  = lane >> 2;
    const int tq = lane & 3;
#pragma unroll
    for (int i = 0; i < 2; i++) {
#pragma unroll
        for (int half = 0; half < 2; half++) {
            int row = bm + wm * 32 + i * 16 + half * 8 + g;
            if (row >= n) continue;
#pragma unroll
            for (int j = 0; j < 8; j++) {
                int col = wn * 64 + j * 8 + tq * 2;
                float vx = c[i][j][half * 2 + 0] + bias[col];
                float vy = c[i][j][half * 2 + 1] + bias[col + 1];
                if (dorelu) {
                    vx = fmaxf(vx, 0.f);
                    vy = fmaxf(vy, 0.f);
                }
                if (C32) {
                    *(float2*)(C32 + (size_t)row * HID + col) = make_float2(vx, vy);
                } else {
                    uint32_t hh, ll;
                    split_pair(vx, vy, hh, ll);
                    *(uint32_t*)(Chi + (size_t)row * HID + col) = hh;
                    *(uint32_t*)(Clo + (size_t)row * HID + col) = ll;
                }
            }
        }
    }
}

// ---------------------------------------------------------------------------
// merged CSR count over all 8 relations
// ---------------------------------------------------------------------------
__global__ void csr_count(const int* __restrict__ eb, const int* __restrict__ es,
                          const int* __restrict__ em, const int* __restrict__ ein,
                          int* __restrict__ cnt)
{
    int e = blockIdx.x * 256 + threadIdx.x;
    if (e >= ETOT) return;
    const int* dstp; int rowOff, le;
    if      (e <  500000) { dstp = eb + 500000;  rowOff = 0;      le = e; }
    else if (e < 1000000) { dstp = eb;           rowOff = 100000; le = e - 500000; }
    else if (e < 1300000) { dstp = es + 300000;  rowOff = 300000; le = e - 1000000; }
    else if (e < 1600000) { dstp = es;           rowOff = 350000; le = e - 1300000; }
    else if (e < 1900000) { dstp = em + 300000;  rowOff = 550000; le = e - 1600000; }
    else if (e < 2200000) { dstp = em;           rowOff = 650000; le = e - 1900000; }
    else if (e < 2300000) { dstp = ein + 100000; rowOff = 700000; le = e - 2200000; }
    else                  { dstp = ein;          rowOff = 702000; le = e - 2300000; }
    atomicAdd(&cnt[rowOff + dstp[le]], 1);
}

__global__ void scan1_kernel(const int* __restrict__ cnt, int* __restrict__ rowptr,
                             int* __restrict__ bsums, int n)
{
    __shared__ int wsums[8];
    int base = blockIdx.x * 4096 + threadIdx.x * 16;
    int v[16];
    int s = 0;
#pragma unroll
    for (int i = 0; i < 16; i++) {
        v[i] = (base + i < n) ? cnt[base + i] : 0;
        s += v[i];
    }
    int lane = threadIdx.x & 31, w = threadIdx.x >> 5;
    int ps = s;
#pragma unroll
    for (int o = 1; o < 32; o <<= 1) {
        int t = __shfl_up_sync(0xffffffffu, ps, o);
        if (lane >= o) ps += t;
    }
    if (lane == 31) wsums[w] = ps;
    __syncthreads();
    if (w == 0) {
        int t = (lane < 8) ? wsums[lane] : 0;
#pragma unroll
        for (int o = 1; o < 8; o <<= 1) {
            int u = __shfl_up_sync(0xffffffffu, t, o);
            if (lane >= o) t += u;
        }
        if (lane < 8) wsums[lane] = t;
    }
    __syncthreads();
    int excl = ps - s + (w ? wsums[w - 1] : 0);
    int run = excl;
#pragma unroll
    for (int i = 0; i < 16; i++) {
        if (base + i < n) rowptr[base + i] = run;
        run += v[i];
    }
    if (threadIdx.x == 0) bsums[blockIdx.x] = wsums[7];
}

__global__ void scan2_kernel(int* __restrict__ bsums, int nb)
{
    if (threadIdx.x == 0 && blockIdx.x == 0) {
        int run = 0;
        for (int i = 0; i < nb; i++) {
            int t = bsums[i];
            bsums[i] = run;
            run += t;
        }
    }
}

__global__ void scan3_kernel(int* __restrict__ rowptr, const int* __restrict__ bsums, int n)
{
    int base = blockIdx.x * 4096 + threadIdx.x * 16;
    int off = bsums[blockIdx.x];
#pragma unroll
    for (int i = 0; i < 16; i++)
        if (base + i < n) rowptr[base + i] += off;
    if (blockIdx.x == 0 && threadIdx.x == 0) rowptr[n] = ETOT;
}

// ---------------------------------------------------------------------------
// merged CSR fill
// ---------------------------------------------------------------------------
__global__ void csr_fill(const int* __restrict__ eb, const int* __restrict__ es,
                         const int* __restrict__ em, const int* __restrict__ ein,
                         const float* __restrict__ w0, const float* __restrict__ w1,
                         const float* __restrict__ w2, const float* __restrict__ w3,
                         const float* __restrict__ w4, const float* __restrict__ w5,
                         const float* __restrict__ w6, const float* __restrict__ w7,
                         int* __restrict__ cursor, int* __restrict__ srcg,
                         float* __restrict__ wg)
{
    int e = blockIdx.x * 256 + threadIdx.x;
    if (e >= ETOT) return;
    const int *dstp, *srcp; const float* ewp; int rowOff, le;
    if      (e <  500000) { dstp = eb + 500000;  srcp = eb;           ewp = w0; rowOff = 0;      le = e; }
    else if (e < 1000000) { dstp = eb;           srcp = eb + 500000;  ewp = w1; rowOff = 100000; le = e - 500000; }
    else if (e < 1300000) { dstp = es + 300000;  srcp = es;           ewp = w2; rowOff = 300000; le = e - 1000000; }
    else if (e < 1600000) { dstp = es;           srcp = es + 300000;  ewp = w3; rowOff = 350000; le = e - 1300000; }
    else if (e < 1900000) { dstp = em + 300000;  srcp = em;           ewp = w4; rowOff = 550000; le = e - 1600000; }
    else if (e < 2200000) { dstp = em;           srcp = em + 300000;  ewp = w5; rowOff = 650000; le = e - 1900000; }
    else if (e < 2300000) { dstp = ein + 100000; srcp = ein;          ewp = w6; rowOff = 700000; le = e - 2200000; }
    else                  { dstp = ein;          srcp = ein + 100000; ewp = w7; rowOff = 702000; le = e - 2300000; }
    int slot = atomicAdd(&cursor[rowOff + dstp[le]], 1);
    srcg[slot] = srcp[le];
    wg[slot]   = ewp[le];
}

// ---------------------------------------------------------------------------
// combined Wl / bias per (layer, dst type)
// ---------------------------------------------------------------------------
__global__ void wsum_kernel(const float* __restrict__ W1l, const float* __restrict__ b1,
                            const float* __restrict__ W2l, const float* __restrict__ b2,
                            float* __restrict__ wsum, float* __restrict__ bsum)
{
    const int dstT[8] = {1, 0, 3, 0, 1, 3, 2, 1};
    int idx = blockIdx.x * blockDim.x + threadIdx.x;
    if (idx >= 2 * 4 * HID * HID) return;
    int l  = idx / (4 * HID * HID);
    int r  = idx % (4 * HID * HID);
    int d  = r / (HID * HID);
    int ij = r % (HID * HID);
    const float* W = l ? W2l : W1l;
    float s = 0.f;
#pragma unroll
    for (int t = 0; t < 8; t++)
        if (dstT[t] == d) s += W[t * HID * HID + ij];
    wsum[idx] = s;
    if (ij < HID) {
        const float* B = l ? b2 : b1;
        float sb = 0.f;
#pragma unroll
        for (int t = 0; t < 8; t++)
            if (dstT[t] == d) sb += B[t * HID + ij];
        bsum[(l * 4 + d) * HID + ij] = sb;
    }
}

__global__ void wsplit_kernel(const float* __restrict__ wsum,
                              const float* __restrict__ W1r,
                              const float* __restrict__ W2r,
                              __nv_bfloat16* __restrict__ wh,
                              __nv_bfloat16* __restrict__ wl)
{
    int idx = blockIdx.x * blockDim.x + threadIdx.x;
    if (idx >= NWCHUNK * HID * HID) return;
    int c  = idx >> 14;
    int ij = idx & 16383;
    float v = (c < 8) ? wsum[idx]
            : (c < 16) ? W1r[(c - 8) * HID * HID + ij]
                       : W2r[(c - 16) * HID * HID + ij];
    __nv_bfloat16 h = __float2bfloat16(v);
    wh[idx] = h;
    wl[idx] = __float2bfloat16(v - __bfloat162float(h));
}

// ---------------------------------------------------------------------------
// split x0 into xhi/xlo at concatenated node offsets
// ---------------------------------------------------------------------------
__global__ void xsplit_kernel(const float* __restrict__ xu, const float* __restrict__ xp,
                              const float* __restrict__ xc, const float* __restrict__ xq,
                              __nv_bfloat16* __restrict__ xhi, __nv_bfloat16* __restrict__ xlo)
{
    int i = blockIdx.x * 256 + threadIdx.x;          // float4 index
    if (i >= NTOT * 32) return;
    int row = i >> 5;
    int c4  = i & 31;
    const float* x;
    int lrow;
    if      (row < NU)           { x = xu; lrow = row; }
    else if (row < NU + NP)      { x = xp; lrow = row - NU; }
    else if (row < NU + NP + NC) { x = xc; lrow = row - NU - NP; }
    else                         { x = xq; lrow = row - NU - NP - NC; }
    float4 v = *((const float4*)(x + (size_t)lrow * HID) + c4);
    uint32_t h01, l01, h23, l23;
    split_pair(v.x, v.y, h01, l01);
    split_pair(v.z, v.w, h23, l23);
    size_t off = (size_t)row * HID + c4 * 4;
    *(uint2*)(xhi + off) = make_uint2(h01, h23);
    *(uint2*)(xlo + off) = make_uint2(l01, l23);
}

// ---------------------------------------------------------------------------
// merged CSR gather (layer 0: fp32 inputs). One warp per (relation,dst) row.
// ---------------------------------------------------------------------------
__global__ void gather_f32(const float* __restrict__ xu, const float* __restrict__ xp,
                           const float* __restrict__ xc, const float* __restrict__ xq,
                           const int* __restrict__ rowptr, const int* __restrict__ srcg,
                           const float* __restrict__ wg,
                           __nv_bfloat16* __restrict__ ahi, __nv_bfloat16* __restrict__ alo)
{
    int row = (blockIdx.x * blockDim.x + threadIdx.x) >> 5;
    int lane = threadIdx.x & 31;
    if (row >= NROWS) return;
    const float* x = (row <  100000) ? xu
                   : (row <  300000) ? xp
                   : (row <  350000) ? xu
                   : (row <  550000) ? xq
                   : (row <  650000) ? xq
                   : (row <  700000) ? xp
                   : (row <  702000) ? xp : xc;

    int e0 = rowptr[row], e1 = rowptr[row + 1];
    float4 acc = make_float4(0.f, 0.f, 0.f, 0.f);
    int e = e0;
    for (; e + 1 < e1; e += 2) {
        int   s0 = srcg[e],  s1 = srcg[e + 1];
        float w0 = wg[e],    w1 = wg[e + 1];
        float4 v0 = *((const float4*)(x + (size_t)s0 * HID) + lane);
        float4 v1 = *((const float4*)(x + (size_t)s1 * HID) + lane);
        acc.x += w0 * v0.x + w1 * v1.x;
        acc.y += w0 * v0.y + w1 * v1.y;
        acc.z += w0 * v0.z + w1 * v1.z;
        acc.w += w0 * v0.w + w1 * v1.w;
    }
    if (e < e1) {
        int s0 = srcg[e];
        float w0 = wg[e];
        float4 v0 = *((const float4*)(x + (size_t)s0 * HID) + lane);
        acc.x += w0 * v0.x; acc.y += w0 * v0.y;
        acc.z += w0 * v0.z; acc.w += w0 * v0.w;
    }
    float invd = 1.f / fmaxf((float)(e1 - e0), 1.f);
    acc.x *= invd; acc.y *= invd; acc.z *= invd; acc.w *= invd;
    uint32_t h01, l01, h23, l23;
    split_pair(acc.x, acc.y, h01, l01);
    split_pair(acc.z, acc.w, h23, l23);
    size_t off = (size_t)row * HID + lane * 4;
    *(uint2*)(ahi + off) = make_uint2(h01, h23);
    *(uint2*)(alo + off) = make_uint2(l01, l23);
}

// ---------------------------------------------------------------------------
// merged CSR gather (layer 1: split-bf16 hidden, reconstructed as hi+lo)
// ---------------------------------------------------------------------------
__global__ void gather_sp(const __nv_bfloat16* __restrict__ hhi,
                          const __nv_bfloat16* __restrict__ hlo,
                          const int* __restrict__ rowptr, const int* __restrict__ srcg,
                          const float* __restrict__ wg,
                          __nv_bfloat16* __restrict__ ahi, __nv_bfloat16* __restrict__ alo)
{
    int row = (blockIdx.x * blockDim.x + threadIdx.x) >> 5;
    int lane = threadIdx.x & 31;
    if (row >= NROWS) return;
    const size_t OU = 0, OP = (size_t)NU * HID, OC = (size_t)(NU + NP) * HID,
                 OQ = (size_t)(NU + NP + NC) * HID;
    size_t xo = (row <  100000) ? OU
              : (row <  300000) ? OP
              : (row <  350000) ? OU
              : (row <  550000) ? OQ
              : (row <  650000) ? OQ
              : (row <  700000) ? OP
              : (row <  702000) ? OP : OC;

    int e0 = rowptr[row], e1 = rowptr[row + 1];
    float4 acc = make_float4(0.f, 0.f, 0.f, 0.f);
    for (int e = e0; e < e1; e++) {
        int   s0 = srcg[e];
        float w0 = wg[e];
        size_t o = xo + (size_t)s0 * HID + lane * 4;
        uint2 uh = *(const uint2*)(hhi + o);
        uint2 ul = *(const uint2*)(hlo + o);
        __nv_bfloat162 h0 = *reinterpret_cast<__nv_bfloat162*>(&uh.x);
        __nv_bfloat162 h1 = *reinterpret_cast<__nv_bfloat162*>(&uh.y);
        __nv_bfloat162 l0 = *reinterpret_cast<__nv_bfloat162*>(&ul.x);
        __nv_bfloat162 l1 = *reinterpret_cast<__nv_bfloat162*>(&ul.y);
        acc.x += w0 * (__bfloat162float(h0.x) + __bfloat162float(l0.x));
        acc.y += w0 * (__bfloat162float(h0.y) + __bfloat162float(l0.y));
        acc.z += w0 * (__bfloat162float(h1.x) + __bfloat162float(l1.x));
        acc.w += w0 * (__bfloat162float(h1.y) + __bfloat162float(l1.y));
    }
    float invd = 1.f / fmaxf((float)(e1 - e0), 1.f);
    acc.x *= invd; acc.y *= invd; acc.z *= invd; acc.w *= invd;
    uint32_t h01, l01, h23, l23;
    split_pair(acc.x, acc.y, h01, l01);
    split_pair(acc.z, acc.w, h23, l23);
    size_t off = (size_t)row * HID + lane * 4;
    *(uint2*)(ahi + off) = make_uint2(h01, h23);
    *(uint2*)(alo + off) = make_uint2(l01, l23);
}

// ---------------------------------------------------------------------------
// host launch
// ---------------------------------------------------------------------------
extern "C" void kernel_launch(void* const* d_in, const int* in_sizes, int n_in,
                              void* d_out, int out_size)
{
    (void)in_sizes; (void)n_in; (void)out_size;

    static const int rowOffR[8] = {0, 100000, 300000, 350000, 550000, 650000, 700000, 702000};
    static const int relForDst[4][3] = { {1, 3, -1}, {0, 4, 7}, {6, -1, -1}, {2, 5, -1} };
    static const int nRelForDst[4]   = { 2, 3, 1, 2 };
    static const int    nodeN[4]   = {NU, NP, NC, NQ};
    static const size_t nodeOff[4] = {0, NU, NU + NP, NU + NP + NC};

    cudaFuncSetAttribute(gemm_mma, cudaFuncAttributeMaxDynamicSharedMemorySize, GSMEM);

    float *wsum, *bsum, *wg;
    __nv_bfloat16 *ahi, *alo, *xhi, *xlo, *wh, *wl;
    int *cnt, *rowptr, *cursor, *srcg, *bsums;
    cudaGetSymbolAddress((void**)&ahi,    g_ahi);
    cudaGetSymbolAddress((void**)&alo,    g_alo);
    cudaGetSymbolAddress((void**)&xhi,    g_xhi);
    cudaGetSymbolAddress((void**)&xlo,    g_xlo);
    cudaGetSymbolAddress((void**)&cnt,    g_cnt);
    cudaGetSymbolAddress((void**)&rowptr, g_rowptr);
    cudaGetSymbolAddress((void**)&cursor, g_cursor);
    cudaGetSymbolAddress((void**)&srcg,   g_srcg);
    cudaGetSymbolAddress((void**)&wg,     g_wg);
    cudaGetSymbolAddress((void**)&bsums,  g_bsums);
    cudaGetSymbolAddress((void**)&wsum,   g_wsum);
    cudaGetSymbolAddress((void**)&bsum,   g_bsum);
    cudaGetSymbolAddress((void**)&wh,     g_wh);
    cudaGetSymbolAddress((void**)&wl,     g_wl);

    const float* xu = (const float*)d_in[0];
    const float* xp = (const float*)d_in[1];
    const float* xc = (const float*)d_in[2];
    const float* xq = (const float*)d_in[3];
    const float* W1l = (const float*)d_in[4];
    const float* b1  = (const float*)d_in[5];
    const float* W1r = (const float*)d_in[6];
    const float* W2l = (const float*)d_in[7];
    const float* b2  = (const float*)d_in[8];
    const float* W2r = (const float*)d_in[9];
    const int* eb  = (const int*)d_in[18];
    const int* es  = (const int*)d_in[19];
    const int* em  = (const int*)d_in[20];
    const int* ein = (const int*)d_in[21];
    float* out = (float*)d_out;

    cudaStream_t st = 0;
    const int NSCAN = (NROWS + 4095) / 4096;

    // ---- CSR build ----
    cudaMemsetAsync(cnt, 0, NROWS * sizeof(int), st);
    csr_count<<<(ETOT + 255) / 256, 256, 0, st>>>(eb, es, em, ein, cnt);
    scan1_kernel<<<NSCAN, 256, 0, st>>>(cnt, rowptr, bsums, NROWS);
    scan2_kernel<<<1, 32, 0, st>>>(bsums, NSCAN);
    scan3_kernel<<<NSCAN, 256, 0, st>>>(rowptr, bsums, NROWS);
    cudaMemcpyAsync(cursor, rowptr, NROWS * sizeof(int), cudaMemcpyDeviceToDevice, st);
    csr_fill<<<(ETOT + 255) / 256, 256, 0, st>>>(
        eb, es, em, ein,
        (const float*)d_in[10], (const float*)d_in[11], (const float*)d_in[12],
        (const float*)d_in[13], (const float*)d_in[14], (const float*)d_in[15],
        (const float*)d_in[16], (const float*)d_in[17],
        cursor, srcg, wg);

    // ---- weights + x split ----
    wsum_kernel<<<(2 * 4 * HID * HID + 255) / 256, 256, 0, st>>>(W1l, b1, W2l, b2, wsum, bsum);
    wsplit_kernel<<<(NWCHUNK * HID * HID + 255) / 256, 256, 0, st>>>(wsum, W1r, W2r, wh, wl);
    xsplit_kernel<<<(NTOT * 32 + 255) / 256, 256, 0, st>>>(xu, xp, xc, xq, xhi, xlo);

    // ---- two layers ----
    for (int layer = 0; layer < 2; layer++) {
        if (layer == 0)
            gather_f32<<<(NROWS * 32 + 255) / 256, 256, 0, st>>>(
                xu, xp, xc, xq, rowptr, srcg, wg, ahi, alo);
        else
            gather_sp<<<(NROWS * 32 + 255) / 256, 256, 0, st>>>(
                xhi, xlo, rowptr, srcg, wg, ahi, alo);

        for (int d = 0; d < 4; d++) {
            const __nv_bfloat16 *Ah[3] = {nullptr, nullptr, nullptr};
            const __nv_bfloat16 *Al[3] = {nullptr, nullptr, nullptr};
            const __nv_bfloat16 *Whp[4] = {nullptr, nullptr, nullptr, nullptr};
            const __nv_bfloat16 *Wlp[4] = {nullptr, nullptr, nullptr, nullptr};
            Whp[0] = wh + (size_t)(layer * 4 + d) * HID * HID;
            Wlp[0] = wl + (size_t)(layer * 4 + d) * HID * HID;
            for (int q = 0; q < nRelForDst[d]; q++) {
                int t = relForDst[d][q];
                Ah[q] = ahi + (size_t)rowOffR[t] * HID;
                Al[q] = alo + (size_t)rowOffR[t] * HID;
                Whp[q + 1] = wh + (size_t)(8 + layer * 8 + t) * HID * HID;
                Wlp[q + 1] = wl + (size_t)(8 + layer * 8 + t) * HID * HID;
            }
            GemmArgs p;
            p.A0h = xhi + nodeOff[d] * HID;  p.A0l = xlo + nodeOff[d] * HID;
            p.A1h = Ah[0]; p.A1l = Al[0];
            p.A2h = Ah[1]; p.A2l = Al[1];
            p.A3h = Ah[2]; p.A3l = Al[2];
            p.W0h = Whp[0]; p.W0l = Wlp[0];
            p.W1h = Whp[1]; p.W1l = Wlp[1];
            p.W2h = Whp[2]; p.W2l = Wlp[2];
            p.W3h = Whp[3]; p.W3l = Wlp[3];
            int nch = 1 + nRelForDst[d];
            float* C32 = layer ? (out + nodeOff[d] * HID) : nullptr;
            __nv_bfloat16* Chi = layer ? nullptr : (xhi + nodeOff[d] * HID);
            __nv_bfloat16* Clo = layer ? nullptr : (xlo + nodeOff[d] * HID);
            gemm_mma<<<(nodeN[d] + 127) / 128, 256, GSMEM, st>>>(
                p, nch, bsum + (layer * 4 + d) * HID, C32, Chi, Clo,
                nodeN[d], layer == 0 ? 1 : 0);
        }
    }
}

// round 8
// speedup vs baseline: 1.0804x; 1.0804x over previous
#include <cuda_runtime.h>
#include <cuda_bf16.h>
#include <stdint.h>

// ---------------------------------------------------------------------------
// HeteroGraphSAGE, 2 layers, 4 node types, 8 relations.
// agg[d] = Wr * (inv[d] * sum_e w_e * x[src]) -> CSR gather (no atomics),
// all GEMM inputs in split-bf16 (hi+lo, fp32-accurate ~2^-16); one K-concat
// mma.sync GEMM per dst type. Single-stage cp.async fills, occupancy 2.
// ---------------------------------------------------------------------------

#define NU 200000
#define NP 100000
#define NC 2000
#define NQ 50000
#define NTOT 352000
#define HID 128

#define NROWS 802000
#define ETOT  2400000
#define NWCHUNK 24

#define LDS 72              // bf16 per smem row (64 data + 8 pad -> 144B pitch)
#define LDSB 144
#define TILE_B (128 * LDSB)          // 18432 B per 128x64 bf16 tile
#define GSMEM (4 * TILE_B)           // Ah, Al, Wh, Wl = 73728 B (occ 2)

// device globals (allocation-free scratch)
__device__ __nv_bfloat16 g_ahi[(size_t)NROWS * HID];
__device__ __nv_bfloat16 g_alo[(size_t)NROWS * HID];
__device__ __nv_bfloat16 g_xhi[(size_t)NTOT * HID];   // x0 split, then h split (in-place)
__device__ __nv_bfloat16 g_xlo[(size_t)NTOT * HID];
__device__ int   g_cnt[NROWS];
__device__ int   g_rowptr[NROWS + 1];
__device__ int   g_cursor[NROWS];
__device__ int   g_srcg[ETOT];
__device__ float g_wg[ETOT];
__device__ int   g_bsums[512];
__device__ float g_wsum[2 * 4 * HID * HID];
__device__ float g_bsum[2 * 4 * HID];
__device__ __nv_bfloat16 g_wh[NWCHUNK * HID * HID];
__device__ __nv_bfloat16 g_wl[NWCHUNK * HID * HID];

// ---------------------------------------------------------------------------
// PTX helpers
// ---------------------------------------------------------------------------
#define LDSM4(R, addr)                                                          \
    asm volatile("ldmatrix.sync.aligned.m8n8.x4.shared.b16 {%0,%1,%2,%3}, [%4];" \
                 : "=r"((R)[0]), "=r"((R)[1]), "=r"((R)[2]), "=r"((R)[3])        \
                 : "r"(addr))

#define MMA16816(C, A, B0, B1)                                                  \
    asm volatile("mma.sync.aligned.m16n8k16.row.col.f32.bf16.bf16.f32 "         \
                 "{%0,%1,%2,%3},{%4,%5,%6,%7},{%8,%9},{%0,%1,%2,%3};"           \
                 : "+f"((C)[0]), "+f"((C)[1]), "+f"((C)[2]), "+f"((C)[3])        \
                 : "r"((A)[0]), "r"((A)[1]), "r"((A)[2]), "r"((A)[3]),           \
                   "r"(B0), "r"(B1))

__device__ __forceinline__ void cpa16(uint32_t dst, const void* src, uint32_t sz)
{
    asm volatile("cp.async.cg.shared.global [%0], [%1], 16, %2;"
                 :: "r"(dst), "l"(src), "r"(sz) : "memory");
}

__device__ __forceinline__ uint32_t pack_bf16(__nv_bfloat16 a, __nv_bfloat16 b)
{
    __nv_bfloat162 p = __halves2bfloat162(a, b);
    return *reinterpret_cast<uint32_t*>(&p);
}

__device__ __forceinline__ void split_pair(float x, float y, uint32_t& hi, uint32_t& lo)
{
    __nv_bfloat16 hx = __float2bfloat16(x);
    __nv_bfloat16 hy = __float2bfloat16(y);
    __nv_bfloat16 lx = __float2bfloat16(x - __bfloat162float(hx));
    __nv_bfloat16 ly = __float2bfloat16(y - __bfloat162float(hy));
    hi = pack_bf16(hx, hy);
    lo = pack_bf16(lx, ly);
}

// ---------------------------------------------------------------------------
// Multi-chunk tensor-core GEMM (bf16x3 split), cp.async fills, occupancy 2:
//   C = bias + sum_ch A_ch @ W_ch^T   (each chunk K=128 as 2 stages of K=64)
// Block tile 128x128, 8 warps (4m x 2n). All inputs pre-split bf16.
// ---------------------------------------------------------------------------
struct GemmArgs {
    const __nv_bfloat16 *A0h, *A0l, *A1h, *A1l, *A2h, *A2l, *A3h, *A3l;
    const __nv_bfloat16 *W0h, *W0l, *W1h, *W1l, *W2h, *W2l, *W3h, *W3l;
};

__global__ void __launch_bounds__(256, 2)
gemm_mma(GemmArgs p, int nch, const float* __restrict__ bias,
         float* __restrict__ C32, __nv_bfloat16* __restrict__ Chi,
         __nv_bfloat16* __restrict__ Clo, int n, int dorelu)
{
    extern __shared__ __nv_bfloat16 smem[];
    uint32_t sb = (uint32_t)__cvta_generic_to_shared(smem);

    const int tid  = threadIdx.x;
    const int lane = tid & 31;
    const int warp = tid >> 5;
    const int wm = warp >> 1;
    const int wn = warp & 1;
    const int bm = blockIdx.x * 128;

    float c[2][8][4];
#pragma unroll
    for (int i = 0; i < 2; i++)
#pragma unroll
        for (int j = 0; j < 8; j++)
#pragma unroll
            for (int q = 0; q < 4; q++) c[i][j][q] = 0.f;

#pragma unroll
    for (int ch = 0; ch < 4; ch++) {
        if (ch < nch) {
            const __nv_bfloat16* Ah = (ch == 0) ? p.A0h : (ch == 1) ? p.A1h
                                    : (ch == 2) ? p.A2h : p.A3h;
            const __nv_bfloat16* Al = (ch == 0) ? p.A0l : (ch == 1) ? p.A1l
                                    : (ch == 2) ? p.A2l : p.A3l;
            const __nv_bfloat16* Wh = (ch == 0) ? p.W0h : (ch == 1) ? p.W1h
                                    : (ch == 2) ? p.W2h : p.W3h;
            const __nv_bfloat16* Wl = (ch == 0) ? p.W0l : (ch == 1) ? p.W1l
                                    : (ch == 2) ? p.W2l : p.W3l;

            for (int kb = 0; kb < 128; kb += 64) {
                // ---- fill via cp.async (pure 16B copies, no reg staging) ----
#pragma unroll
                for (int it = 0; it < 4; it++) {
                    int idx = tid + it * 256;          // granule 0..1023
                    int r   = idx >> 3;                // row 0..127
                    int c16 = idx & 7;                 // 16B col group
                    uint32_t so = r * LDSB + c16 * 16;
                    int grow = bm + r;
                    int rowc = (grow < n) ? grow : (n > 0 ? n - 1 : 0);
                    uint32_t ok = (grow < n) ? 16u : 0u;
                    size_t ga = (size_t)rowc * HID + kb + c16 * 8;
                    size_t gw = (size_t)r * HID + kb + c16 * 8;
                    cpa16(sb + so,              Ah + ga, ok);
                    cpa16(sb + TILE_B + so,     Al + ga, ok);
                    cpa16(sb + 2 * TILE_B + so, Wh + gw, 16u);
                    cpa16(sb + 3 * TILE_B + so, Wl + gw, 16u);
                }
                asm volatile("cp.async.commit_group;" ::: "memory");
                asm volatile("cp.async.wait_group 0;" ::: "memory");
                __syncthreads();

                // ---- 4 k-steps of 16 ----
#pragma unroll
                for (int ks = 0; ks < 4; ks++) {
                    uint32_t ah[2][4], al[2][4], bh[4][4], bl[4][4];
#pragma unroll
                    for (int i = 0; i < 2; i++) {
                        int r   = wm * 32 + i * 16 + (lane & 15);
                        int kby = ks * 32 + ((lane >> 4) << 4);
                        uint32_t ad = sb + r * LDSB + kby;
                        LDSM4(ah[i], ad);
                        LDSM4(al[i], ad + TILE_B);
                    }
#pragma unroll
                    for (int pq = 0; pq < 4; pq++) {
                        int nr  = wn * 64 + (2 * pq + (lane >> 4)) * 8 + (lane & 7);
                        int kby = ks * 32 + ((lane >> 3) & 1) * 16;
                        uint32_t ad = sb + 2 * TILE_B + nr * LDSB + kby;
                        LDSM4(bh[pq], ad);
                        LDSM4(bl[pq], ad + TILE_B);
                    }
#pragma unroll
                    for (int i = 0; i < 2; i++)
#pragma unroll
                        for (int j = 0; j < 8; j++) {
                            const uint32_t* b = bh[j >> 1] + (j & 1) * 2;
                            MMA16816(c[i][j], ah[i], b[0], b[1]);
                        }
#pragma unroll
                    for (int i = 0; i < 2; i++)
#pragma unroll
                        for (int j = 0; j < 8; j++) {
                            const uint32_t* b = bl[j >> 1] + (j & 1) * 2;
                            MMA16816(c[i][j], ah[i], b[0], b[1]);
                        }
#pragma unroll
                    for (int i = 0; i < 2; i++)
#pragma unroll
                        for (int j = 0; j < 8; j++) {
                            const uint32_t* b = bh[j >> 1] + (j & 1) * 2;
                            MMA16816(c[i][j], al[i], b[0], b[1]);
                        }
                }
                __syncthreads();
            }
        }
    }

    // ---- epilogue ----
    const int g  = lane >> 2;
    const int tq = lane & 3;
#pragma unroll
    for (int i = 0; i < 2; i++) {
#pragma unroll
        for (int half = 0; half < 2; half++) {
            int row = bm + wm * 32 + i * 16 + half * 8 + g;
            if (row >= n) continue;
#pragma unroll
            for (int j = 0; j < 8; j++) {
                int col = wn * 64 + j * 8 + tq * 2;
                float vx = c[i][j][half * 2 + 0] + bias[col];
                float vy = c[i][j][half * 2 + 1] + bias[col + 1];
                if (dorelu) {
                    vx = fmaxf(vx, 0.f);
                    vy = fmaxf(vy, 0.f);
                }
                if (C32) {
                    *(float2*)(C32 + (size_t)row * HID + col) = make_float2(vx, vy);
                } else {
                    uint32_t hh, ll;
                    split_pair(vx, vy, hh, ll);
                    *(uint32_t*)(Chi + (size_t)row * HID + col) = hh;
                    *(uint32_t*)(Clo + (size_t)row * HID + col) = ll;
                }
            }
        }
    }
}

// ---------------------------------------------------------------------------
// merged CSR count over all 8 relations
// ---------------------------------------------------------------------------
__global__ void csr_count(const int* __restrict__ eb, const int* __restrict__ es,
                          const int* __restrict__ em, const int* __restrict__ ein,
                          int* __restrict__ cnt)
{
    int e = blockIdx.x * 256 + threadIdx.x;
    if (e >= ETOT) return;
    const int* dstp; int rowOff, le;
    if      (e <  500000) { dstp = eb + 500000;  rowOff = 0;      le = e; }
    else if (e < 1000000) { dstp = eb;           rowOff = 100000; le = e - 500000; }
    else if (e < 1300000) { dstp = es + 300000;  rowOff = 300000; le = e - 1000000; }
    else if (e < 1600000) { dstp = es;           rowOff = 350000; le = e - 1300000; }
    else if (e < 1900000) { dstp = em + 300000;  rowOff = 550000; le = e - 1600000; }
    else if (e < 2200000) { dstp = em;           rowOff = 650000; le = e - 1900000; }
    else if (e < 2300000) { dstp = ein + 100000; rowOff = 700000; le = e - 2200000; }
    else                  { dstp = ein;          rowOff = 702000; le = e - 2300000; }
    atomicAdd(&cnt[rowOff + dstp[le]], 1);
}

__global__ void scan1_kernel(const int* __restrict__ cnt, int* __restrict__ rowptr,
                             int* __restrict__ bsums, int n)
{
    __shared__ int wsums[8];
    int base = blockIdx.x * 4096 + threadIdx.x * 16;
    int v[16];
    int s = 0;
#pragma unroll
    for (int i = 0; i < 16; i++) {
        v[i] = (base + i < n) ? cnt[base + i] : 0;
        s += v[i];
    }
    int lane = threadIdx.x & 31, w = threadIdx.x >> 5;
    int ps = s;
#pragma unroll
    for (int o = 1; o < 32; o <<= 1) {
        int t = __shfl_up_sync(0xffffffffu, ps, o);
        if (lane >= o) ps += t;
    }
    if (lane == 31) wsums[w] = ps;
    __syncthreads();
    if (w == 0) {
        int t = (lane < 8) ? wsums[lane] : 0;
#pragma unroll
        for (int o = 1; o < 8; o <<= 1) {
            int u = __shfl_up_sync(0xffffffffu, t, o);
            if (lane >= o) t += u;
        }
        if (lane < 8) wsums[lane] = t;
    }
    __syncthreads();
    int excl = ps - s + (w ? wsums[w - 1] : 0);
    int run = excl;
#pragma unroll
    for (int i = 0; i < 16; i++) {
        if (base + i < n) rowptr[base + i] = run;
        run += v[i];
    }
    if (threadIdx.x == 0) bsums[blockIdx.x] = wsums[7];
}

__global__ void scan2_kernel(int* __restrict__ bsums, int nb)
{
    if (threadIdx.x == 0 && blockIdx.x == 0) {
        int run = 0;
        for (int i = 0; i < nb; i++) {
            int t = bsums[i];
            bsums[i] = run;
            run += t;
        }
    }
}

__global__ void scan3_kernel(int* __restrict__ rowptr, const int* __restrict__ bsums, int n)
{
    int base = blockIdx.x * 4096 + threadIdx.x * 16;
    int off = bsums[blockIdx.x];
#pragma unroll
    for (int i = 0; i < 16; i++)
        if (base + i < n) rowptr[base + i] += off;
    if (blockIdx.x == 0 && threadIdx.x == 0) rowptr[n] = ETOT;
}

// ---------------------------------------------------------------------------
// merged CSR fill
// ---------------------------------------------------------------------------
__global__ void csr_fill(const int* __restrict__ eb, const int* __restrict__ es,
                         const int* __restrict__ em, const int* __restrict__ ein,
                         const float* __restrict__ w0, const float* __restrict__ w1,
                         const float* __restrict__ w2, const float* __restrict__ w3,
                         const float* __restrict__ w4, const float* __restrict__ w5,
                         const float* __restrict__ w6, const float* __restrict__ w7,
                         int* __restrict__ cursor, int* __restrict__ srcg,
                         float* __restrict__ wg)
{
    int e = blockIdx.x * 256 + threadIdx.x;
    if (e >= ETOT) return;
    const int *dstp, *srcp; const float* ewp; int rowOff, le;
    if      (e <  500000) { dstp = eb + 500000;  srcp = eb;           ewp = w0; rowOff = 0;      le = e; }
    else if (e < 1000000) { dstp = eb;           srcp = eb + 500000;  ewp = w1; rowOff = 100000; le = e - 500000; }
    else if (e < 1300000) { dstp = es + 300000;  srcp = es;           ewp = w2; rowOff = 300000; le = e - 1000000; }
    else if (e < 1600000) { dstp = es;           srcp = es + 300000;  ewp = w3; rowOff = 350000; le = e - 1300000; }
    else if (e < 1900000) { dstp = em + 300000;  srcp = em;           ewp = w4; rowOff = 550000; le = e - 1600000; }
    else if (e < 2200000) { dstp = em;           srcp = em + 300000;  ewp = w5; rowOff = 650000; le = e - 1900000; }
    else if (e < 2300000) { dstp = ein + 100000; srcp = ein;          ewp = w6; rowOff = 700000; le = e - 2200000; }
    else                  { dstp = ein;          srcp = ein + 100000; ewp = w7; rowOff = 702000; le = e - 2300000; }
    int slot = atomicAdd(&cursor[rowOff + dstp[le]], 1);
    srcg[slot] = srcp[le];
    wg[slot]   = ewp[le];
}

// ---------------------------------------------------------------------------
// combined Wl / bias per (layer, dst type)
// ---------------------------------------------------------------------------
__global__ void wsum_kernel(const float* __restrict__ W1l, const float* __restrict__ b1,
                            const float* __restrict__ W2l, const float* __restrict__ b2,
                            float* __restrict__ wsum, float* __restrict__ bsum)
{
    const int dstT[8] = {1, 0, 3, 0, 1, 3, 2, 1};
    int idx = blockIdx.x * blockDim.x + threadIdx.x;
    if (idx >= 2 * 4 * HID * HID) return;
    int l  = idx / (4 * HID * HID);
    int r  = idx % (4 * HID * HID);
    int d  = r / (HID * HID);
    int ij = r % (HID * HID);
    const float* W = l ? W2l : W1l;
    float s = 0.f;
#pragma unroll
    for (int t = 0; t < 8; t++)
        if (dstT[t] == d) s += W[t * HID * HID + ij];
    wsum[idx] = s;
    if (ij < HID) {
        const float* B = l ? b2 : b1;
        float sb = 0.f;
#pragma unroll
        for (int t = 0; t < 8; t++)
            if (dstT[t] == d) sb += B[t * HID + ij];
        bsum[(l * 4 + d) * HID + ij] = sb;
    }
}

__global__ void wsplit_kernel(const float* __restrict__ wsum,
                              const float* __restrict__ W1r,
                              const float* __restrict__ W2r,
                              __nv_bfloat16* __restrict__ wh,
                              __nv_bfloat16* __restrict__ wl)
{
    int idx = blockIdx.x * blockDim.x + threadIdx.x;
    if (idx >= NWCHUNK * HID * HID) return;
    int c  = idx >> 14;
    int ij = idx & 16383;
    float v = (c < 8) ? wsum[idx]
            : (c < 16) ? W1r[(c - 8) * HID * HID + ij]
                       : W2r[(c - 16) * HID * HID + ij];
    __nv_bfloat16 h = __float2bfloat16(v);
    wh[idx] = h;
    wl[idx] = __float2bfloat16(v - __bfloat162float(h));
}

// ---------------------------------------------------------------------------
// split x0 into xhi/xlo at concatenated node offsets
// ---------------------------------------------------------------------------
__global__ void xsplit_kernel(const float* __restrict__ xu, const float* __restrict__ xp,
                              const float* __restrict__ xc, const float* __restrict__ xq,
                              __nv_bfloat16* __restrict__ xhi, __nv_bfloat16* __restrict__ xlo)
{
    int i = blockIdx.x * 256 + threadIdx.x;          // float4 index
    if (i >= NTOT * 32) return;
    int row = i >> 5;
    int c4  = i & 31;
    const float* x;
    int lrow;
    if      (row < NU)           { x = xu; lrow = row; }
    else if (row < NU + NP)      { x = xp; lrow = row - NU; }
    else if (row < NU + NP + NC) { x = xc; lrow = row - NU - NP; }
    else                         { x = xq; lrow = row - NU - NP - NC; }
    float4 v = *((const float4*)(x + (size_t)lrow * HID) + c4);
    uint32_t h01, l01, h23, l23;
    split_pair(v.x, v.y, h01, l01);
    split_pair(v.z, v.w, h23, l23);
    size_t off = (size_t)row * HID + c4 * 4;
    *(uint2*)(xhi + off) = make_uint2(h01, h23);
    *(uint2*)(xlo + off) = make_uint2(l01, l23);
}

// ---------------------------------------------------------------------------
// merged CSR gather (layer 0: fp32 inputs). One warp per (relation,dst) row.
// ---------------------------------------------------------------------------
__global__ void gather_f32(const float* __restrict__ xu, const float* __restrict__ xp,
                           const float* __restrict__ xc, const float* __restrict__ xq,
                           const int* __restrict__ rowptr, const int* __restrict__ srcg,
                           const float* __restrict__ wg,
                           __nv_bfloat16* __restrict__ ahi, __nv_bfloat16* __restrict__ alo)
{
    int row = (blockIdx.x * blockDim.x + threadIdx.x) >> 5;
    int lane = threadIdx.x & 31;
    if (row >= NROWS) return;
    const float* x = (row <  100000) ? xu
                   : (row <  300000) ? xp
                   : (row <  350000) ? xu
                   : (row <  550000) ? xq
                   : (row <  650000) ? xq
                   : (row <  700000) ? xp
                   : (row <  702000) ? xp : xc;

    int e0 = rowptr[row], e1 = rowptr[row + 1];
    float4 acc = make_float4(0.f, 0.f, 0.f, 0.f);
    int e = e0;
    for (; e + 1 < e1; e += 2) {
        int   s0 = srcg[e],  s1 = srcg[e + 1];
        float w0 = wg[e],    w1 = wg[e + 1];
        float4 v0 = *((const float4*)(x + (size_t)s0 * HID) + lane);
        float4 v1 = *((const float4*)(x + (size_t)s1 * HID) + lane);
        acc.x += w0 * v0.x + w1 * v1.x;
        acc.y += w0 * v0.y + w1 * v1.y;
        acc.z += w0 * v0.z + w1 * v1.z;
        acc.w += w0 * v0.w + w1 * v1.w;
    }
    if (e < e1) {
        int s0 = srcg[e];
        float w0 = wg[e];
        float4 v0 = *((const float4*)(x + (size_t)s0 * HID) + lane);
        acc.x += w0 * v0.x; acc.y += w0 * v0.y;
        acc.z += w0 * v0.z; acc.w += w0 * v0.w;
    }
    float invd = 1.f / fmaxf((float)(e1 - e0), 1.f);
    acc.x *= invd; acc.y *= invd; acc.z *= invd; acc.w *= invd;
    uint32_t h01, l01, h23, l23;
    split_pair(acc.x, acc.y, h01, l01);
    split_pair(acc.z, acc.w, h23, l23);
    size_t off = (size_t)row * HID + lane * 4;
    *(uint2*)(ahi + off) = make_uint2(h01, h23);
    *(uint2*)(alo + off) = make_uint2(l01, l23);
}

// ---------------------------------------------------------------------------
// merged CSR gather (layer 1: split-bf16 hidden, reconstructed as hi+lo)
// ---------------------------------------------------------------------------
__global__ void gather_sp(const __nv_bfloat16* __restrict__ hhi,
                          const __nv_bfloat16* __restrict__ hlo,
                          const int* __restrict__ rowptr, const int* __restrict__ srcg,
                          const float* __restrict__ wg,
                          __nv_bfloat16* __restrict__ ahi, __nv_bfloat16* __restrict__ alo)
{
    int row = (blockIdx.x * blockDim.x + threadIdx.x) >> 5;
    int lane = threadIdx.x & 31;
    if (row >= NROWS) return;
    const size_t OU = 0, OP = (size_t)NU * HID, OC = (size_t)(NU + NP) * HID,
                 OQ = (size_t)(NU + NP + NC) * HID;
    size_t xo = (row <  100000) ? OU
              : (row <  300000) ? OP
              : (row <  350000) ? OU
              : (row <  550000) ? OQ
              : (row <  650000) ? OQ
              : (row <  700000) ? OP
              : (row <  702000) ? OP : OC;

    int e0 = rowptr[row], e1 = rowptr[row + 1];
    float4 acc = make_float4(0.f, 0.f, 0.f, 0.f);
    for (int e = e0; e < e1; e++) {
        int   s0 = srcg[e];
        float w0 = wg[e];
        size_t o = xo + (size_t)s0 * HID + lane * 4;
        uint2 uh = *(const uint2*)(hhi + o);
        uint2 ul = *(const uint2*)(hlo + o);
        __nv_bfloat162 h0 = *reinterpret_cast<__nv_bfloat162*>(&uh.x);
        __nv_bfloat162 h1 = *reinterpret_cast<__nv_bfloat162*>(&uh.y);
        __nv_bfloat162 l0 = *reinterpret_cast<__nv_bfloat162*>(&ul.x);
        __nv_bfloat162 l1 = *reinterpret_cast<__nv_bfloat162*>(&ul.y);
        acc.x += w0 * (__bfloat162float(h0.x) + __bfloat162float(l0.x));
        acc.y += w0 * (__bfloat162float(h0.y) + __bfloat162float(l0.y));
        acc.z += w0 * (__bfloat162float(h1.x) + __bfloat162float(l1.x));
        acc.w += w0 * (__bfloat162float(h1.y) + __bfloat162float(l1.y));
    }
    float invd = 1.f / fmaxf((float)(e1 - e0), 1.f);
    acc.x *= invd; acc.y *= invd; acc.z *= invd; acc.w *= invd;
    uint32_t h01, l01, h23, l23;
    split_pair(acc.x, acc.y, h01, l01);
    split_pair(acc.z, acc.w, h23, l23);
    size_t off = (size_t)row * HID + lane * 4;
    *(uint2*)(ahi + off) = make_uint2(h01, h23);
    *(uint2*)(alo + off) = make_uint2(l01, l23);
}

// ---------------------------------------------------------------------------
// host launch
// ---------------------------------------------------------------------------
extern "C" void kernel_launch(void* const* d_in, const int* in_sizes, int n_in,
                              void* d_out, int out_size)
{
    (void)in_sizes; (void)n_in; (void)out_size;

    static const int rowOffR[8] = {0, 100000, 300000, 350000, 550000, 650000, 700000, 702000};
    static const int relForDst[4][3] = { {1, 3, -1}, {0, 4, 7}, {6, -1, -1}, {2, 5, -1} };
    static const int nRelForDst[4]   = { 2, 3, 1, 2 };
    static const int    nodeN[4]   = {NU, NP, NC, NQ};
    static const size_t nodeOff[4] = {0, NU, NU + NP, NU + NP + NC};

    cudaFuncSetAttribute(gemm_mma, cudaFuncAttributeMaxDynamicSharedMemorySize, GSMEM);

    float *wsum, *bsum, *wg;
    __nv_bfloat16 *ahi, *alo, *xhi, *xlo, *wh, *wl;
    int *cnt, *rowptr, *cursor, *srcg, *bsums;
    cudaGetSymbolAddress((void**)&ahi,    g_ahi);
    cudaGetSymbolAddress((void**)&alo,    g_alo);
    cudaGetSymbolAddress((void**)&xhi,    g_xhi);
    cudaGetSymbolAddress((void**)&xlo,    g_xlo);
    cudaGetSymbolAddress((void**)&cnt,    g_cnt);
    cudaGetSymbolAddress((void**)&rowptr, g_rowptr);
    cudaGetSymbolAddress((void**)&cursor, g_cursor);
    cudaGetSymbolAddress((void**)&srcg,   g_srcg);
    cudaGetSymbolAddress((void**)&wg,     g_wg);
    cudaGetSymbolAddress((void**)&bsums,  g_bsums);
    cudaGetSymbolAddress((void**)&wsum,   g_wsum);
    cudaGetSymbolAddress((void**)&bsum,   g_bsum);
    cudaGetSymbolAddress((void**)&wh,     g_wh);
    cudaGetSymbolAddress((void**)&wl,     g_wl);

    const float* xu = (const float*)d_in[0];
    const float* xp = (const float*)d_in[1];
    const float* xc = (const float*)d_in[2];
    const float* xq = (const float*)d_in[3];
    const float* W1l = (const float*)d_in[4];
    const float* b1  = (const float*)d_in[5];
    const float* W1r = (const float*)d_in[6];
    const float* W2l = (const float*)d_in[7];
    const float* b2  = (const float*)d_in[8];
    const float* W2r = (const float*)d_in[9];
    const int* eb  = (const int*)d_in[18];
    const int* es  = (const int*)d_in[19];
    const int* em  = (const int*)d_in[20];
    const int* ein = (const int*)d_in[21];
    float* out = (float*)d_out;

    cudaStream_t st = 0;
    const int NSCAN = (NROWS + 4095) / 4096;

    // ---- CSR build ----
    cudaMemsetAsync(cnt, 0, NROWS * sizeof(int), st);
    csr_count<<<(ETOT + 255) / 256, 256, 0, st>>>(eb, es, em, ein, cnt);
    scan1_kernel<<<NSCAN, 256, 0, st>>>(cnt, rowptr, bsums, NROWS);
    scan2_kernel<<<1, 32, 0, st>>>(bsums, NSCAN);
    scan3_kernel<<<NSCAN, 256, 0, st>>>(rowptr, bsums, NROWS);
    cudaMemcpyAsync(cursor, rowptr, NROWS * sizeof(int), cudaMemcpyDeviceToDevice, st);
    csr_fill<<<(ETOT + 255) / 256, 256, 0, st>>>(
        eb, es, em, ein,
        (const float*)d_in[10], (const float*)d_in[11], (const float*)d_in[12],
        (const float*)d_in[13], (const float*)d_in[14], (const float*)d_in[15],
        (const float*)d_in[16], (const float*)d_in[17],
        cursor, srcg, wg);

    // ---- weights + x split ----
    wsum_kernel<<<(2 * 4 * HID * HID + 255) / 256, 256, 0, st>>>(W1l, b1, W2l, b2, wsum, bsum);
    wsplit_kernel<<<(NWCHUNK * HID * HID + 255) / 256, 256, 0, st>>>(wsum, W1r, W2r, wh, wl);
    xsplit_kernel<<<(NTOT * 32 + 255) / 256, 256, 0, st>>>(xu, xp, xc, xq, xhi, xlo);

    // ---- two layers ----
    for (int layer = 0; layer < 2; layer++) {
        if (layer == 0)
            gather_f32<<<(NROWS * 32 + 255) / 256, 256, 0, st>>>(
                xu, xp, xc, xq, rowptr, srcg, wg, ahi, alo);
        else
            gather_sp<<<(NROWS * 32 + 255) / 256, 256, 0, st>>>(
                xhi, xlo, rowptr, srcg, wg, ahi, alo);

        for (int d = 0; d < 4; d++) {
            const __nv_bfloat16 *Ah[3] = {nullptr, nullptr, nullptr};
            const __nv_bfloat16 *Al[3] = {nullptr, nullptr, nullptr};
            const __nv_bfloat16 *Whp[4] = {nullptr, nullptr, nullptr, nullptr};
            const __nv_bfloat16 *Wlp[4] = {nullptr, nullptr, nullptr, nullptr};
            Whp[0] = wh + (size_t)(layer * 4 + d) * HID * HID;
            Wlp[0] = wl + (size_t)(layer * 4 + d) * HID * HID;
            for (int q = 0; q < nRelForDst[d]; q++) {
                int t = relForDst[d][q];
                Ah[q] = ahi + (size_t)rowOffR[t] * HID;
                Al[q] = alo + (size_t)rowOffR[t] * HID;
                Whp[q + 1] = wh + (size_t)(8 + layer * 8 + t) * HID * HID;
                Wlp[q + 1] = wl + (size_t)(8 + layer * 8 + t) * HID * HID;
            }
            GemmArgs p;
            p.A0h = xhi + nodeOff[d] * HID;  p.A0l = xlo + nodeOff[d] * HID;
            p.A1h = Ah[0]; p.A1l = Al[0];
            p.A2h = Ah[1]; p.A2l = Al[1];
            p.A3h = Ah[2]; p.A3l = Al[2];
            p.W0h = Whp[0]; p.W0l = Wlp[0];
            p.W1h = Whp[1]; p.W1l = Wlp[1];
            p.W2h = Whp[2]; p.W2l = Wlp[2];
            p.W3h = Whp[3]; p.W3l = Wlp[3];
            int nch = 1 + nRelForDst[d];
            float* C32 = layer ? (out + nodeOff[d] * HID) : nullptr;
            __nv_bfloat16* Chi = layer ? nullptr : (xhi + nodeOff[d] * HID);
            __nv_bfloat16* Clo = layer ? nullptr : (xlo + nodeOff[d] * HID);
            gemm_mma<<<(nodeN[d] + 127) / 128, 256, GSMEM, st>>>(
                p, nch, bsum + (layer * 4 + d) * HID, C32, Chi, Clo,
                nodeN[d], layer == 0 ? 1 : 0);
        }
    }
}